// round 12
// baseline (speedup 1.0000x reference)
#include <cuda_runtime.h>

// TimeSeriesWineSNN: 3-layer LIF SNN, T=1000, B=4096, dims 8 -> 28 -> 8 -> 4.
// R12 = R10's proven bit-exact SCALAR arithmetic (rounded products, butterfly
// association, fma membrane) + R11's bit-neutral structural wins:
//   - direct float4 x loads (no broadcast shuffles)
//   - s2 exchange via smem (no shuffles)
//   - running output pointers
//   - pad adds dropped in layer-2 tree; direct (m > 1) comparators

constexpr int T_STEPS = 1000;
constexpr int BATCH   = 4096;
constexpr int NIN     = 8;
constexpr int NH1     = 28;
constexpr int NH2     = 8;
constexpr int NOUT    = 4;

// lane-0 value of a shfl-down butterfly over 8 lanes (offsets 4,2,1)
__device__ __forceinline__ float butterfly8(const float* __restrict__ p) {
    float v0 = __fadd_rn(p[0], p[4]);
    float v1 = __fadd_rn(p[1], p[5]);
    float v2 = __fadd_rn(p[2], p[6]);
    float v3 = __fadd_rn(p[3], p[7]);
    v0 = __fadd_rn(v0, v2);
    v1 = __fadd_rn(v1, v3);
    return __fadd_rn(v0, v1);
}

__global__ void __launch_bounds__(128)
snn_kernel(const float* __restrict__ x,
           const float* __restrict__ W1, const float* __restrict__ b1,
           const float* __restrict__ W2, const float* __restrict__ b2,
           const float* __restrict__ W3, const float* __restrict__ b3,
           float* __restrict__ out)
{
    const int tid = blockIdx.x * 128 + threadIdx.x;
    const int j   = tid & 7;          // lane within 8-thread group
    const int b   = tid >> 3;         // batch element
    const int lg  = threadIdx.x >> 3; // local group index 0..15

    __shared__ __align__(16) float s1buf[2][16][32];
    __shared__ __align__(16) float s2buf[2][16][8];

    // ---- weights into registers (fake neurons n >= 28 get zero weights) ----
    float w1[4][8], bias1[4];
#pragma unroll
    for (int r = 0; r < 4; ++r) {
        const int n = 4 * j + r;
        const bool v = (n < NH1);
        bias1[r] = v ? __ldg(&b1[n]) : 0.0f;
#pragma unroll
        for (int i = 0; i < 8; ++i)
            w1[r][i] = v ? __ldg(&W1[n * NIN + i]) : 0.0f;
    }
    float w2[NH1];
#pragma unroll
    for (int k = 0; k < NH1; ++k) w2[k] = __ldg(&W2[j * NH1 + k]);
    const float bias2 = __ldg(&b2[j]);

    const bool j4 = (j < 4);
    float w3[8];
#pragma unroll
    for (int i = 0; i < 8; ++i) w3[i] = j4 ? __ldg(&W3[j * NH2 + i]) : 0.0f;
    const float bias3 = j4 ? __ldg(&b3[j]) : 0.0f;

    // ---- state ----
    float m1[4] = {0.f, 0.f, 0.f, 0.f};
    float m2 = 0.f, m3 = 0.f;

    // ---- output regions: mem3 | spk3 | spk1 | spk2 (running pointers) ----
    float* mem3p = out                                  + (size_t)b * NOUT + j;
    float* spk3p = out + (size_t)T_STEPS * BATCH * NOUT + (size_t)b * NOUT + j;
    float* spk1p = out + 2ull * T_STEPS * BATCH * NOUT  + (size_t)b * NH1 + 4 * j;
    float* spk2p = out + 2ull * T_STEPS * BATCH * NOUT
                       + (size_t)T_STEPS * BATCH * NH1  + (size_t)b * NH2 + j;
    constexpr size_t S1STRIDE = (size_t)BATCH * NH1;   // per-t element strides
    constexpr size_t S2STRIDE = (size_t)BATCH * NH2;
    constexpr size_t O3STRIDE = (size_t)BATCH * NOUT;

    // x as float4 pairs; all 8 lanes of a group read the same 32B (L1 broadcast)
    const float4* __restrict__ xq = reinterpret_cast<const float4*>(x) + (size_t)b * 2;
    constexpr size_t XSTRIDE4 = (size_t)BATCH * NIN / 4;  // float4 per timestep

    // prefetch ring (depth 2 timesteps)
    float4 ra0 = xq[0],        rb0 = xq[1];
    float4 ra1 = xq[XSTRIDE4], rb1 = xq[XSTRIDE4 + 1];

    // LIF: reset from previous m; contracted leak+integrate; exact -1.0; spike on new m.
    // (m > 1.0f) is equivalent to (fsub(m,1) > 0) in fp32: a positive nonzero
    // difference never rounds to <= 0 at this magnitude.
    auto lif = [](float& m, float cur, float& spk) {
        const float mo = m;
        float mn = __fmaf_rn(0.9f, mo, cur);
        if (mo > 1.0f) mn = __fsub_rn(mn, 1.0f);
        m = mn;
        spk = (mn > 1.0f) ? 1.0f : 0.0f;
    };

    auto step = [&](float4 xa, float4 xb, int bufi) {
        const float xs[8] = {xa.x, xa.y, xa.z, xa.w, xb.x, xb.y, xb.z, xb.w};

        // ---- layer 1: 4 neurons/lane; rounded products, butterfly-8, bias last ----
        float4 sp;
        float* spv = &sp.x;
#pragma unroll
        for (int r = 0; r < 4; ++r) {
            float p[8];
#pragma unroll
            for (int i = 0; i < 8; ++i)
                p[i] = __fmul_rn(w1[r][i], xs[i]);
            float c = __fadd_rn(butterfly8(p), bias1[r]);
            lif(m1[r], c, spv[r]);
        }

        // s1 exchange (lane 7 writes pad cols 28..31: always 0.0, zero-weighted)
        *reinterpret_cast<float4*>(&s1buf[bufi][lg][4 * j]) = sp;
        if (j < 7)
            *reinterpret_cast<float4*>(spk1p) = sp;
        __syncwarp();

        // ---- layer 2: rounded products, width-32 butterfly (v[28..31] = 0) ----
        float v[28];
#pragma unroll
        for (int q = 0; q < 7; ++q) {
            float4 s = *reinterpret_cast<const float4*>(&s1buf[bufi][lg][4 * q]);
            v[4 * q + 0] = __fmul_rn(w2[4 * q + 0], s.x);
            v[4 * q + 1] = __fmul_rn(w2[4 * q + 1], s.y);
            v[4 * q + 2] = __fmul_rn(w2[4 * q + 2], s.z);
            v[4 * q + 3] = __fmul_rn(w2[4 * q + 3], s.w);
        }
        // offset 16: v[i] += v[i+16] for i<12 (i=12..15 add +0: dropped, bit-safe)
        float q0[16];
#pragma unroll
        for (int i = 0; i < 12; ++i) q0[i] = __fadd_rn(v[i], v[i + 16]);
#pragma unroll
        for (int i = 12; i < 16; ++i) q0[i] = v[i];
        // offset 8
        float r0[8];
#pragma unroll
        for (int i = 0; i < 8; ++i) r0[i] = __fadd_rn(q0[i], q0[i + 8]);
        // offset 4
        float s4[4];
#pragma unroll
        for (int i = 0; i < 4; ++i) s4[i] = __fadd_rn(r0[i], r0[i + 4]);
        // offset 2, 1, bias
        float t0 = __fadd_rn(s4[0], s4[2]);
        float t1 = __fadd_rn(s4[1], s4[3]);
        float a2 = __fadd_rn(__fadd_rn(t0, t1), bias2);

        float s2;
        lif(m2, a2, s2);
        *spk2p = s2;
        s2buf[bufi][lg][j] = s2;
        __syncwarp();

        // ---- layer 3: rounded products over smem s2, butterfly-8, bias last ----
        float4 sa = *reinterpret_cast<const float4*>(&s2buf[bufi][lg][0]);
        float4 sb = *reinterpret_cast<const float4*>(&s2buf[bufi][lg][4]);
        float p3[8];
        p3[0] = __fmul_rn(w3[0], sa.x);
        p3[1] = __fmul_rn(w3[1], sa.y);
        p3[2] = __fmul_rn(w3[2], sa.z);
        p3[3] = __fmul_rn(w3[3], sa.w);
        p3[4] = __fmul_rn(w3[4], sb.x);
        p3[5] = __fmul_rn(w3[5], sb.y);
        p3[6] = __fmul_rn(w3[6], sb.z);
        p3[7] = __fmul_rn(w3[7], sb.w);
        float a3 = __fadd_rn(butterfly8(p3), bias3);

        float s3;
        lif(m3, a3, s3);
        if (j4) {
            *mem3p = m3;
            *spk3p = s3;
        }

        // advance running pointers
        spk1p += S1STRIDE;
        spk2p += S2STRIDE;
        mem3p += O3STRIDE;
        spk3p += O3STRIDE;
    };

    for (int t = 0; t < T_STEPS; t += 2) {
        const float4 a0 = ra0, b0 = rb0, a1 = ra1, b1 = rb1;
        if (t + 2 < T_STEPS) {
            const float4* p = xq + (size_t)(t + 2) * XSTRIDE4;
            ra0 = p[0];
            rb0 = p[1];
            ra1 = p[XSTRIDE4];
            rb1 = p[XSTRIDE4 + 1];
        }
        step(a0, b0, 0);
        step(a1, b1, 1);
    }
}

extern "C" void kernel_launch(void* const* d_in, const int* in_sizes, int n_in,
                              void* d_out, int out_size) {
    const float* x  = (const float*)d_in[0];
    const float* W1 = (const float*)d_in[1];
    const float* b1 = (const float*)d_in[2];
    const float* W2 = (const float*)d_in[3];
    const float* b2 = (const float*)d_in[4];
    const float* W3 = (const float*)d_in[5];
    const float* b3 = (const float*)d_in[6];

    const int threads = 128;
    const int blocks  = (BATCH * 8) / threads;  // 256
    snn_kernel<<<blocks, threads>>>(x, W1, b1, W2, b2, W3, b3, (float*)d_out);
}

// round 13
// speedup vs baseline: 1.3982x; 1.3982x over previous
#include <cuda_runtime.h>

// TimeSeriesWineSNN: 3-layer LIF SNN, T=1000, B=4096, dims 8 -> 28 -> 8 -> 4.
// R13 = R10's proven bit-exact scalar arithmetic (rounded products, butterfly
// association, fma membrane, shfl exchanges) + software pipelining:
//   stage A(t+1) [layer 1] is interleaved with stage B(t) [layers 2+3],
//   hiding the sync/LDS/SHFL latency chain behind L1's independent FP work.
// 4-slot smem ring (t&3) keeps the exchange race-free without extra syncs.
// Bit-safe trims kept from R12: running pointers, pad-add removal, (m>1) cmps.

constexpr int T_STEPS = 1000;
constexpr int BATCH   = 4096;
constexpr int NIN     = 8;
constexpr int NH1     = 28;
constexpr int NH2     = 8;
constexpr int NOUT    = 4;

// lane-0 value of a shfl-down butterfly over 8 lanes (offsets 4,2,1)
__device__ __forceinline__ float butterfly8(const float* __restrict__ p) {
    float v0 = __fadd_rn(p[0], p[4]);
    float v1 = __fadd_rn(p[1], p[5]);
    float v2 = __fadd_rn(p[2], p[6]);
    float v3 = __fadd_rn(p[3], p[7]);
    v0 = __fadd_rn(v0, v2);
    v1 = __fadd_rn(v1, v3);
    return __fadd_rn(v0, v1);
}

__global__ void __launch_bounds__(128)
snn_kernel(const float* __restrict__ x,
           const float* __restrict__ W1, const float* __restrict__ b1,
           const float* __restrict__ W2, const float* __restrict__ b2,
           const float* __restrict__ W3, const float* __restrict__ b3,
           float* __restrict__ out)
{
    const int tid = blockIdx.x * 128 + threadIdx.x;
    const int j   = tid & 7;          // lane within 8-thread group
    const int b   = tid >> 3;         // batch element
    const int lg  = threadIdx.x >> 3; // local group index 0..15

    __shared__ __align__(16) float s1buf[4][16][32];   // 4-slot ring (t & 3)

    // ---- weights into registers (fake neurons n >= 28 get zero weights) ----
    float w1[4][8], bias1[4];
#pragma unroll
    for (int r = 0; r < 4; ++r) {
        const int n = 4 * j + r;
        const bool v = (n < NH1);
        bias1[r] = v ? __ldg(&b1[n]) : 0.0f;
#pragma unroll
        for (int i = 0; i < 8; ++i)
            w1[r][i] = v ? __ldg(&W1[n * NIN + i]) : 0.0f;
    }
    float w2[NH1];
#pragma unroll
    for (int k = 0; k < NH1; ++k) w2[k] = __ldg(&W2[j * NH1 + k]);
    const float bias2 = __ldg(&b2[j]);

    const bool j4 = (j < 4);
    float w3[8];
#pragma unroll
    for (int i = 0; i < 8; ++i) w3[i] = j4 ? __ldg(&W3[j * NH2 + i]) : 0.0f;
    const float bias3 = j4 ? __ldg(&b3[j]) : 0.0f;

    // ---- state ----
    float m1[4] = {0.f, 0.f, 0.f, 0.f};
    float m2 = 0.f, m3 = 0.f;

    // ---- output regions: mem3 | spk3 | spk1 | spk2 (running pointers) ----
    float* mem3p = out                                  + (size_t)b * NOUT + j;
    float* spk3p = out + (size_t)T_STEPS * BATCH * NOUT + (size_t)b * NOUT + j;
    float* spk1p = out + 2ull * T_STEPS * BATCH * NOUT  + (size_t)b * NH1 + 4 * j;
    float* spk2p = out + 2ull * T_STEPS * BATCH * NOUT
                       + (size_t)T_STEPS * BATCH * NH1  + (size_t)b * NH2 + j;
    constexpr size_t S1STRIDE = (size_t)BATCH * NH1;   // per-t element strides
    constexpr size_t S2STRIDE = (size_t)BATCH * NH2;
    constexpr size_t O3STRIDE = (size_t)BATCH * NOUT;

    const float* __restrict__ xp = x + (size_t)b * NIN + j;
    const size_t xstride = (size_t)BATCH * NIN;   // elements per timestep

    // LIF: reset from previous m; contracted leak+integrate; exact -1.0 subtract;
    // spike on new m. (m > 1.0f) == (fsub(m,1) > 0) in fp32 (verified bit-safe R12).
    auto lif = [](float& m, float cur, float& spk) {
        const float mo = m;
        float mn = __fmaf_rn(0.9f, mo, cur);
        if (mo > 1.0f) mn = __fsub_rn(mn, 1.0f);
        m = mn;
        spk = (mn > 1.0f) ? 1.0f : 0.0f;
    };

    // ---- stage A: layer 1 for one timestep; writes s1 ring + spk1 ----
    auto stageA = [&](float xval, int bufi) {
        float xs[8];
#pragma unroll
        for (int i = 0; i < 8; ++i)
            xs[i] = __shfl_sync(0xffffffffu, xval, i, 8);

        float4 sp;
        float* spv = &sp.x;
#pragma unroll
        for (int r = 0; r < 4; ++r) {
            float p[8];
#pragma unroll
            for (int i = 0; i < 8; ++i)
                p[i] = __fmul_rn(w1[r][i], xs[i]);
            float c = __fadd_rn(butterfly8(p), bias1[r]);
            lif(m1[r], c, spv[r]);
        }

        *reinterpret_cast<float4*>(&s1buf[bufi][lg][4 * j]) = sp;
        if (j < 7)
            *reinterpret_cast<float4*>(spk1p) = sp;
        spk1p += S1STRIDE;
        __syncwarp();
    };

    // ---- stage B: layers 2+3 for one timestep; reads s1 ring ----
    auto stageB = [&](int bufi) {
        float v[28];
#pragma unroll
        for (int q = 0; q < 7; ++q) {
            float4 s = *reinterpret_cast<const float4*>(&s1buf[bufi][lg][4 * q]);
            v[4 * q + 0] = __fmul_rn(w2[4 * q + 0], s.x);
            v[4 * q + 1] = __fmul_rn(w2[4 * q + 1], s.y);
            v[4 * q + 2] = __fmul_rn(w2[4 * q + 2], s.z);
            v[4 * q + 3] = __fmul_rn(w2[4 * q + 3], s.w);
        }
        // width-32 butterfly with slots 28..31 = +0 (pad adds dropped; bit-safe)
        float q0[16];
#pragma unroll
        for (int i = 0; i < 12; ++i) q0[i] = __fadd_rn(v[i], v[i + 16]);
#pragma unroll
        for (int i = 12; i < 16; ++i) q0[i] = v[i];
        float r0[8];
#pragma unroll
        for (int i = 0; i < 8; ++i) r0[i] = __fadd_rn(q0[i], q0[i + 8]);
        float s4[4];
#pragma unroll
        for (int i = 0; i < 4; ++i) s4[i] = __fadd_rn(r0[i], r0[i + 4]);
        float t0 = __fadd_rn(s4[0], s4[2]);
        float t1 = __fadd_rn(s4[1], s4[3]);
        float a2 = __fadd_rn(__fadd_rn(t0, t1), bias2);

        float s2;
        lif(m2, a2, s2);
        *spk2p = s2;
        spk2p += S2STRIDE;

        float p3[8];
#pragma unroll
        for (int i = 0; i < 8; ++i)
            p3[i] = __fmul_rn(w3[i], __shfl_sync(0xffffffffu, s2, i, 8));
        float a3 = __fadd_rn(butterfly8(p3), bias3);

        float s3;
        lif(m3, a3, s3);
        if (j4) {
            *mem3p = m3;
            *spk3p = s3;
        }
        mem3p += O3STRIDE;
        spk3p += O3STRIDE;
    };

    // ---- pipelined main loop: A runs one step ahead of B ----
    // prologue: A(0); pf holds x(1..4)
    {
        float x0 = xp[0];
        stageA(x0, 0);
    }
    float pf[4];
#pragma unroll
    for (int i = 0; i < 4; ++i) pf[i] = xp[(size_t)(1 + i) * xstride];

    for (int tb = 0; tb < T_STEPS; tb += 4) {
        const float a1 = pf[0], a2x = pf[1], a3x = pf[2], a4 = pf[3];
        // prefetch x(tb+5 .. tb+8)
#pragma unroll
        for (int i = 0; i < 4; ++i) {
            const int tn = tb + 5 + i;
            if (tn < T_STEPS) pf[i] = xp[(size_t)tn * xstride];
        }

        stageA(a1,  (tb + 1) & 3); stageB(tb & 3);
        stageA(a2x, (tb + 2) & 3); stageB((tb + 1) & 3);
        stageA(a3x, (tb + 3) & 3); stageB((tb + 2) & 3);
        if (tb + 4 < T_STEPS) stageA(a4, (tb + 4) & 3);
        stageB((tb + 3) & 3);
    }
}

extern "C" void kernel_launch(void* const* d_in, const int* in_sizes, int n_in,
                              void* d_out, int out_size) {
    const float* x  = (const float*)d_in[0];
    const float* W1 = (const float*)d_in[1];
    const float* b1 = (const float*)d_in[2];
    const float* W2 = (const float*)d_in[3];
    const float* b2 = (const float*)d_in[4];
    const float* W3 = (const float*)d_in[5];
    const float* b3 = (const float*)d_in[6];

    const int threads = 128;
    const int blocks  = (BATCH * 8) / threads;  // 256
    snn_kernel<<<blocks, threads>>>(x, W1, b1, W2, b2, W3, b3, (float*)d_out);
}

// round 14
// speedup vs baseline: 1.4216x; 1.0167x over previous
#include <cuda_runtime.h>

// TimeSeriesWineSNN: 3-layer LIF SNN, T=1000, B=4096, dims 8 -> 28 -> 8 -> 4.
// R14 = R13's bit-exact arithmetic, warp-specialized across a 2-warp pipeline:
//   warp A: layer 1 (+ s1 smem write + spk1 store), one step ahead
//   warp B: layers 2+3 (+ spk2/mem3/spk3 stores)
//   handoff: 2-slot smem ring + one named bar.sync(pair, 64) per step
// Doubles resident warps (1024 -> 2048) at constant total issue slots.

constexpr int T_STEPS = 1000;
constexpr int BATCH   = 4096;
constexpr int NIN     = 8;
constexpr int NH1     = 28;
constexpr int NH2     = 8;
constexpr int NOUT    = 4;

constexpr int BLOCK_THREADS = 256;           // 8 warps = 4 A/B pairs
constexpr int BATCHES_PER_BLOCK = 16;        // 4 pairs x 4 batch groups

// lane-0 value of a shfl-down butterfly over 8 lanes (offsets 4,2,1)
__device__ __forceinline__ float butterfly8(const float* __restrict__ p) {
    float v0 = __fadd_rn(p[0], p[4]);
    float v1 = __fadd_rn(p[1], p[5]);
    float v2 = __fadd_rn(p[2], p[6]);
    float v3 = __fadd_rn(p[3], p[7]);
    v0 = __fadd_rn(v0, v2);
    v1 = __fadd_rn(v1, v3);
    return __fadd_rn(v0, v1);
}

// LIF (bit-exact R13): reset from previous m; contracted leak+integrate;
// exact -1.0 subtract; spike on new m.
__device__ __forceinline__ void lif(float& m, float cur, float& spk) {
    const float mo = m;
    float mn = __fmaf_rn(0.9f, mo, cur);
    if (mo > 1.0f) mn = __fsub_rn(mn, 1.0f);
    m = mn;
    spk = (mn > 1.0f) ? 1.0f : 0.0f;
}

__device__ __forceinline__ void bar_pair(int barid) {
    asm volatile("bar.sync %0, 64;" :: "r"(barid) : "memory");
}

__global__ void __launch_bounds__(BLOCK_THREADS)
snn_kernel(const float* __restrict__ x,
           const float* __restrict__ W1, const float* __restrict__ b1,
           const float* __restrict__ W2, const float* __restrict__ b2,
           const float* __restrict__ W3, const float* __restrict__ b3,
           float* __restrict__ out)
{
    const int warp = threadIdx.x >> 5;
    const int pair = warp >> 1;              // 0..3
    const bool isA = (warp & 1) == 0;
    const int lane = threadIdx.x & 31;
    const int j    = lane & 7;               // lane within 8-thread group
    const int g    = lane >> 3;              // batch group within warp 0..3
    const int b    = blockIdx.x * BATCHES_PER_BLOCK + pair * 4 + g;
    const int grow = pair * 4 + g;           // smem group row 0..15
    const int barid = 1 + pair;              // named barrier per pair

    __shared__ __align__(16) float s1buf[2][BATCHES_PER_BLOCK][32];  // 2-slot ring

    constexpr size_t S1STRIDE = (size_t)BATCH * NH1;   // per-t element strides
    constexpr size_t S2STRIDE = (size_t)BATCH * NH2;
    constexpr size_t O3STRIDE = (size_t)BATCH * NOUT;

    if (isA) {
        // ================= WARP A: layer 1 =================
        float w1[4][8], bias1[4];
#pragma unroll
        for (int r = 0; r < 4; ++r) {
            const int n = 4 * j + r;
            const bool v = (n < NH1);
            bias1[r] = v ? __ldg(&b1[n]) : 0.0f;
#pragma unroll
            for (int i = 0; i < 8; ++i)
                w1[r][i] = v ? __ldg(&W1[n * NIN + i]) : 0.0f;
        }
        float m1[4] = {0.f, 0.f, 0.f, 0.f};

        float* spk1p = out + 2ull * T_STEPS * BATCH * NOUT + (size_t)b * NH1 + 4 * j;

        const float* __restrict__ xp = x + (size_t)b * NIN + j;
        const size_t xstride = (size_t)BATCH * NIN;

        float pf0 = xp[0];
        float pf1 = xp[xstride];
        float pf2 = xp[2 * xstride];
        float pf3 = xp[3 * xstride];

        auto stageA = [&](float xval, int slot) {
            float xs[8];
#pragma unroll
            for (int i = 0; i < 8; ++i)
                xs[i] = __shfl_sync(0xffffffffu, xval, i, 8);

            float4 sp;
            float* spv = &sp.x;
#pragma unroll
            for (int r = 0; r < 4; ++r) {
                float p[8];
#pragma unroll
                for (int i = 0; i < 8; ++i)
                    p[i] = __fmul_rn(w1[r][i], xs[i]);
                float c = __fadd_rn(butterfly8(p), bias1[r]);
                lif(m1[r], c, spv[r]);
            }

            *reinterpret_cast<float4*>(&s1buf[slot][grow][4 * j]) = sp;
            if (j < 7)
                *reinterpret_cast<float4*>(spk1p) = sp;
            spk1p += S1STRIDE;
            bar_pair(barid);   // publish slot to warp B (drains STS)
        };

        for (int tb = 0; tb < T_STEPS; tb += 4) {
            const float a0 = pf0, a1 = pf1, a2 = pf2, a3 = pf3;
            if (tb + 4 < T_STEPS) {
                const float* p = xp + (size_t)(tb + 4) * xstride;
                pf0 = p[0];
                pf1 = p[xstride];
                pf2 = p[2 * xstride];
                pf3 = p[3 * xstride];
            }
            stageA(a0, (tb + 0) & 1);
            stageA(a1, (tb + 1) & 1);
            stageA(a2, (tb + 2) & 1);
            stageA(a3, (tb + 3) & 1);
        }
    } else {
        // ================= WARP B: layers 2 + 3 =================
        float w2[NH1];
#pragma unroll
        for (int k = 0; k < NH1; ++k) w2[k] = __ldg(&W2[j * NH1 + k]);
        const float bias2 = __ldg(&b2[j]);

        const bool j4 = (j < 4);
        float w3[8];
#pragma unroll
        for (int i = 0; i < 8; ++i) w3[i] = j4 ? __ldg(&W3[j * NH2 + i]) : 0.0f;
        const float bias3 = j4 ? __ldg(&b3[j]) : 0.0f;

        float m2 = 0.f, m3 = 0.f;

        float* mem3p = out                                  + (size_t)b * NOUT + j;
        float* spk3p = out + (size_t)T_STEPS * BATCH * NOUT + (size_t)b * NOUT + j;
        float* spk2p = out + 2ull * T_STEPS * BATCH * NOUT
                           + (size_t)T_STEPS * BATCH * NH1  + (size_t)b * NH2 + j;

        auto stageB = [&](int slot) {
            bar_pair(barid);   // wait for warp A's slot
            float v[28];
#pragma unroll
            for (int q = 0; q < 7; ++q) {
                float4 s = *reinterpret_cast<const float4*>(&s1buf[slot][grow][4 * q]);
                v[4 * q + 0] = __fmul_rn(w2[4 * q + 0], s.x);
                v[4 * q + 1] = __fmul_rn(w2[4 * q + 1], s.y);
                v[4 * q + 2] = __fmul_rn(w2[4 * q + 2], s.z);
                v[4 * q + 3] = __fmul_rn(w2[4 * q + 3], s.w);
            }
            // width-32 butterfly with slots 28..31 = +0 (pad adds dropped; bit-safe)
            float q0[16];
#pragma unroll
            for (int i = 0; i < 12; ++i) q0[i] = __fadd_rn(v[i], v[i + 16]);
#pragma unroll
            for (int i = 12; i < 16; ++i) q0[i] = v[i];
            float r0[8];
#pragma unroll
            for (int i = 0; i < 8; ++i) r0[i] = __fadd_rn(q0[i], q0[i + 8]);
            float s4[4];
#pragma unroll
            for (int i = 0; i < 4; ++i) s4[i] = __fadd_rn(r0[i], r0[i + 4]);
            float t0 = __fadd_rn(s4[0], s4[2]);
            float t1 = __fadd_rn(s4[1], s4[3]);
            float a2 = __fadd_rn(__fadd_rn(t0, t1), bias2);

            float s2;
            lif(m2, a2, s2);
            *spk2p = s2;
            spk2p += S2STRIDE;

            float p3[8];
#pragma unroll
            for (int i = 0; i < 8; ++i)
                p3[i] = __fmul_rn(w3[i], __shfl_sync(0xffffffffu, s2, i, 8));
            float a3 = __fadd_rn(butterfly8(p3), bias3);

            float s3;
            lif(m3, a3, s3);
            if (j4) {
                *mem3p = m3;
                *spk3p = s3;
            }
            mem3p += O3STRIDE;
            spk3p += O3STRIDE;
        };

        for (int tb = 0; tb < T_STEPS; tb += 4) {
            stageB((tb + 0) & 1);
            stageB((tb + 1) & 1);
            stageB((tb + 2) & 1);
            stageB((tb + 3) & 1);
        }
    }
}

extern "C" void kernel_launch(void* const* d_in, const int* in_sizes, int n_in,
                              void* d_out, int out_size) {
    const float* x  = (const float*)d_in[0];
    const float* W1 = (const float*)d_in[1];
    const float* b1 = (const float*)d_in[2];
    const float* W2 = (const float*)d_in[3];
    const float* b2 = (const float*)d_in[4];
    const float* W3 = (const float*)d_in[5];
    const float* b3 = (const float*)d_in[6];

    const int blocks = BATCH / BATCHES_PER_BLOCK;  // 256
    snn_kernel<<<blocks, BLOCK_THREADS>>>(x, W1, b1, W2, b2, W3, b3, (float*)d_out);
}

// round 15
// speedup vs baseline: 1.5775x; 1.1097x over previous
#include <cuda_runtime.h>

// TimeSeriesWineSNN: 3-layer LIF SNN, T=1000, B=4096, dims 8 -> 28 -> 8 -> 4.
// R15 = R14 (warp-specialized A/B pipeline) with:
//   - 2 timesteps per barrier (4-slot smem ring): halves rendezvous count
//   - FFMA-folded butterfly LEAF in layers 2/3 (bit-exact: spike products are
//     exactly representable, so fma == mul+add there)
// Arithmetic otherwise byte-identical to the proven 4.4e-9 configuration.

constexpr int T_STEPS = 1000;
constexpr int BATCH   = 4096;
constexpr int NIN     = 8;
constexpr int NH1     = 28;
constexpr int NH2     = 8;
constexpr int NOUT    = 4;

constexpr int BLOCK_THREADS = 256;           // 8 warps = 4 A/B pairs
constexpr int BATCHES_PER_BLOCK = 16;        // 4 pairs x 4 batch groups

// lane-0 value of a shfl-down butterfly over 8 lanes (offsets 4,2,1)
__device__ __forceinline__ float butterfly8(const float* __restrict__ p) {
    float v0 = __fadd_rn(p[0], p[4]);
    float v1 = __fadd_rn(p[1], p[5]);
    float v2 = __fadd_rn(p[2], p[6]);
    float v3 = __fadd_rn(p[3], p[7]);
    v0 = __fadd_rn(v0, v2);
    v1 = __fadd_rn(v1, v3);
    return __fadd_rn(v0, v1);
}

// LIF (bit-exact): reset from previous m; contracted leak+integrate;
// exact -1.0 subtract; spike on new m.
__device__ __forceinline__ void lif(float& m, float cur, float& spk) {
    const float mo = m;
    float mn = __fmaf_rn(0.9f, mo, cur);
    if (mo > 1.0f) mn = __fsub_rn(mn, 1.0f);
    m = mn;
    spk = (mn > 1.0f) ? 1.0f : 0.0f;
}

__device__ __forceinline__ void bar_pair(int barid) {
    asm volatile("bar.sync %0, 64;" :: "r"(barid) : "memory");
}

__global__ void __launch_bounds__(BLOCK_THREADS)
snn_kernel(const float* __restrict__ x,
           const float* __restrict__ W1, const float* __restrict__ b1,
           const float* __restrict__ W2, const float* __restrict__ b2,
           const float* __restrict__ W3, const float* __restrict__ b3,
           float* __restrict__ out)
{
    const int warp = threadIdx.x >> 5;
    const int pair = warp >> 1;              // 0..3
    const bool isA = (warp & 1) == 0;
    const int lane = threadIdx.x & 31;
    const int j    = lane & 7;               // lane within 8-thread group
    const int g    = lane >> 3;              // batch group within warp 0..3
    const int b    = blockIdx.x * BATCHES_PER_BLOCK + pair * 4 + g;
    const int grow = pair * 4 + g;           // smem group row 0..15
    const int barid = 1 + pair;              // named barrier per pair

    __shared__ __align__(16) float s1buf[4][BATCHES_PER_BLOCK][32];  // 4-slot ring

    constexpr size_t S1STRIDE = (size_t)BATCH * NH1;   // per-t element strides
    constexpr size_t S2STRIDE = (size_t)BATCH * NH2;
    constexpr size_t O3STRIDE = (size_t)BATCH * NOUT;

    if (isA) {
        // ================= WARP A: layer 1, runs up to 2 steps ahead =========
        float w1[4][8], bias1[4];
#pragma unroll
        for (int r = 0; r < 4; ++r) {
            const int n = 4 * j + r;
            const bool v = (n < NH1);
            bias1[r] = v ? __ldg(&b1[n]) : 0.0f;
#pragma unroll
            for (int i = 0; i < 8; ++i)
                w1[r][i] = v ? __ldg(&W1[n * NIN + i]) : 0.0f;
        }
        float m1[4] = {0.f, 0.f, 0.f, 0.f};

        float* spk1p = out + 2ull * T_STEPS * BATCH * NOUT + (size_t)b * NH1 + 4 * j;

        const float* __restrict__ xp = x + (size_t)b * NIN + j;
        const size_t xstride = (size_t)BATCH * NIN;

        float pf0 = xp[0];
        float pf1 = xp[xstride];
        float pf2 = xp[2 * xstride];
        float pf3 = xp[3 * xstride];

        auto stepA = [&](float xval, int slot) {
            float xs[8];
#pragma unroll
            for (int i = 0; i < 8; ++i)
                xs[i] = __shfl_sync(0xffffffffu, xval, i, 8);

            float4 sp;
            float* spv = &sp.x;
#pragma unroll
            for (int r = 0; r < 4; ++r) {
                float p[8];
#pragma unroll
                for (int i = 0; i < 8; ++i)
                    p[i] = __fmul_rn(w1[r][i], xs[i]);
                float c = __fadd_rn(butterfly8(p), bias1[r]);
                lif(m1[r], c, spv[r]);
            }

            *reinterpret_cast<float4*>(&s1buf[slot][grow][4 * j]) = sp;
            if (j < 7)
                *reinterpret_cast<float4*>(spk1p) = sp;
            spk1p += S1STRIDE;
        };

        for (int tb = 0; tb < T_STEPS; tb += 4) {
            const float a0 = pf0, a1 = pf1, a2 = pf2, a3 = pf3;
            if (tb + 4 < T_STEPS) {
                const float* p = xp + (size_t)(tb + 4) * xstride;
                pf0 = p[0];
                pf1 = p[xstride];
                pf2 = p[2 * xstride];
                pf3 = p[3 * xstride];
            }
            stepA(a0, 0); stepA(a1, 1); bar_pair(barid);   // publish slots 0,1
            stepA(a2, 2); stepA(a3, 3); bar_pair(barid);   // publish slots 2,3
        }
    } else {
        // ================= WARP B: layers 2 + 3 =================
        float w2[NH1];
#pragma unroll
        for (int k = 0; k < NH1; ++k) w2[k] = __ldg(&W2[j * NH1 + k]);
        const float bias2 = __ldg(&b2[j]);

        const bool j4 = (j < 4);
        float w3[8];
#pragma unroll
        for (int i = 0; i < 8; ++i) w3[i] = j4 ? __ldg(&W3[j * NH2 + i]) : 0.0f;
        const float bias3 = j4 ? __ldg(&b3[j]) : 0.0f;

        float m2 = 0.f, m3 = 0.f;

        float* mem3p = out                                  + (size_t)b * NOUT + j;
        float* spk3p = out + (size_t)T_STEPS * BATCH * NOUT + (size_t)b * NOUT + j;
        float* spk2p = out + 2ull * T_STEPS * BATCH * NOUT
                           + (size_t)T_STEPS * BATCH * NH1  + (size_t)b * NH2 + j;

        auto stepB = [&](int slot) {
            float s1v[28];
#pragma unroll
            for (int q = 0; q < 7; ++q) {
                float4 s = *reinterpret_cast<const float4*>(&s1buf[slot][grow][4 * q]);
                s1v[4 * q + 0] = s.x; s1v[4 * q + 1] = s.y;
                s1v[4 * q + 2] = s.z; s1v[4 * q + 3] = s.w;
            }
            // width-32 butterfly; LEAF FFMA-folded (products exact for 0/1 spikes):
            //   q0[i] = round(w2[i]*s[i] + w2[i+16]*s[i+16])  == mul+add bitwise
            float q0[16];
#pragma unroll
            for (int i = 0; i < 12; ++i)
                q0[i] = __fmaf_rn(w2[i], s1v[i], __fmul_rn(w2[i + 16], s1v[i + 16]));
#pragma unroll
            for (int i = 12; i < 16; ++i)
                q0[i] = __fmul_rn(w2[i], s1v[i]);
            float r0[8];
#pragma unroll
            for (int i = 0; i < 8; ++i) r0[i] = __fadd_rn(q0[i], q0[i + 8]);
            float s4[4];
#pragma unroll
            for (int i = 0; i < 4; ++i) s4[i] = __fadd_rn(r0[i], r0[i + 4]);
            float t0 = __fadd_rn(s4[0], s4[2]);
            float t1 = __fadd_rn(s4[1], s4[3]);
            float a2 = __fadd_rn(__fadd_rn(t0, t1), bias2);

            float s2;
            lif(m2, a2, s2);
            *spk2p = s2;
            spk2p += S2STRIDE;

            // layer 3: butterfly-8 with FFMA-folded leaf (s2 exact 0/1)
            float sv[8];
#pragma unroll
            for (int i = 0; i < 8; ++i)
                sv[i] = __shfl_sync(0xffffffffu, s2, i, 8);
            float v0 = __fmaf_rn(w3[0], sv[0], __fmul_rn(w3[4], sv[4]));
            float v1 = __fmaf_rn(w3[1], sv[1], __fmul_rn(w3[5], sv[5]));
            float v2 = __fmaf_rn(w3[2], sv[2], __fmul_rn(w3[6], sv[6]));
            float v3 = __fmaf_rn(w3[3], sv[3], __fmul_rn(w3[7], sv[7]));
            v0 = __fadd_rn(v0, v2);
            v1 = __fadd_rn(v1, v3);
            float a3 = __fadd_rn(__fadd_rn(v0, v1), bias3);

            float s3;
            lif(m3, a3, s3);
            if (j4) {
                *mem3p = m3;
                *spk3p = s3;
            }
            mem3p += O3STRIDE;
            spk3p += O3STRIDE;
        };

        for (int tb = 0; tb < T_STEPS; tb += 4) {
            bar_pair(barid); stepB(0); stepB(1);
            bar_pair(barid); stepB(2); stepB(3);
        }
    }
}

extern "C" void kernel_launch(void* const* d_in, const int* in_sizes, int n_in,
                              void* d_out, int out_size) {
    const float* x  = (const float*)d_in[0];
    const float* W1 = (const float*)d_in[1];
    const float* b1 = (const float*)d_in[2];
    const float* W2 = (const float*)d_in[3];
    const float* b2 = (const float*)d_in[4];
    const float* W3 = (const float*)d_in[5];
    const float* b3 = (const float*)d_in[6];

    const int blocks = BATCH / BATCHES_PER_BLOCK;  // 256
    snn_kernel<<<blocks, BLOCK_THREADS>>>(x, W1, b1, W2, b2, W3, b3, (float*)d_out);
}

// round 16
// speedup vs baseline: 1.6355x; 1.0367x over previous
#include <cuda_runtime.h>

// TimeSeriesWineSNN: 3-layer LIF SNN, T=1000, B=4096, dims 8 -> 28 -> 8 -> 4.
// R16 = R15 (warp-specialized A/B pipeline, bit-exact 4.4e-9 arithmetic) with:
//   - bar every 4 timesteps (8-slot smem ring): ~250 fewer rendezvous
//   - layer 3 via ballot+SEL (replaces 8 SHFLs; bit-exact: products of 0/1
//     spikes are exact, +/-0 differences are absorbed before any comparator)
//   - FFMA-folded layer-2 leaf kept (bit-exact for 0/1 spikes)

constexpr int T_STEPS = 1000;
constexpr int BATCH   = 4096;
constexpr int NIN     = 8;
constexpr int NH1     = 28;
constexpr int NH2     = 8;
constexpr int NOUT    = 4;

constexpr int BLOCK_THREADS = 256;           // 8 warps = 4 A/B pairs
constexpr int BATCHES_PER_BLOCK = 16;        // 4 pairs x 4 batch groups

// lane-0 value of a shfl-down butterfly over 8 lanes (offsets 4,2,1)
__device__ __forceinline__ float butterfly8(const float* __restrict__ p) {
    float v0 = __fadd_rn(p[0], p[4]);
    float v1 = __fadd_rn(p[1], p[5]);
    float v2 = __fadd_rn(p[2], p[6]);
    float v3 = __fadd_rn(p[3], p[7]);
    v0 = __fadd_rn(v0, v2);
    v1 = __fadd_rn(v1, v3);
    return __fadd_rn(v0, v1);
}

// LIF (bit-exact): reset from previous m; contracted leak+integrate;
// exact -1.0 subtract; spike on new m.
__device__ __forceinline__ void lif(float& m, float cur, float& spk) {
    const float mo = m;
    float mn = __fmaf_rn(0.9f, mo, cur);
    if (mo > 1.0f) mn = __fsub_rn(mn, 1.0f);
    m = mn;
    spk = (mn > 1.0f) ? 1.0f : 0.0f;
}

__device__ __forceinline__ void bar_pair(int barid) {
    asm volatile("bar.sync %0, 64;" :: "r"(barid) : "memory");
}

__global__ void __launch_bounds__(BLOCK_THREADS)
snn_kernel(const float* __restrict__ x,
           const float* __restrict__ W1, const float* __restrict__ b1,
           const float* __restrict__ W2, const float* __restrict__ b2,
           const float* __restrict__ W3, const float* __restrict__ b3,
           float* __restrict__ out)
{
    const int warp = threadIdx.x >> 5;
    const int pair = warp >> 1;              // 0..3
    const bool isA = (warp & 1) == 0;
    const int lane = threadIdx.x & 31;
    const int j    = lane & 7;               // lane within 8-thread group
    const int g    = lane >> 3;              // batch group within warp 0..3
    const int b    = blockIdx.x * BATCHES_PER_BLOCK + pair * 4 + g;
    const int grow = pair * 4 + g;           // smem group row 0..15
    const int barid = 1 + pair;              // named barrier per pair

    __shared__ __align__(16) float s1buf[8][BATCHES_PER_BLOCK][32];  // 8-slot ring

    constexpr size_t S1STRIDE = (size_t)BATCH * NH1;   // per-t element strides
    constexpr size_t S2STRIDE = (size_t)BATCH * NH2;
    constexpr size_t O3STRIDE = (size_t)BATCH * NOUT;

    if (isA) {
        // ====== WARP A: layer 1; publishes 4 slots per barrier ======
        float w1[4][8], bias1[4];
#pragma unroll
        for (int r = 0; r < 4; ++r) {
            const int n = 4 * j + r;
            const bool v = (n < NH1);
            bias1[r] = v ? __ldg(&b1[n]) : 0.0f;
#pragma unroll
            for (int i = 0; i < 8; ++i)
                w1[r][i] = v ? __ldg(&W1[n * NIN + i]) : 0.0f;
        }
        float m1[4] = {0.f, 0.f, 0.f, 0.f};

        float* spk1p = out + 2ull * T_STEPS * BATCH * NOUT + (size_t)b * NH1 + 4 * j;

        const float* __restrict__ xp = x + (size_t)b * NIN + j;
        const size_t xstride = (size_t)BATCH * NIN;

        float pf0 = xp[0];
        float pf1 = xp[xstride];
        float pf2 = xp[2 * xstride];
        float pf3 = xp[3 * xstride];

        auto stepA = [&](float xval, int slot) {
            float xs[8];
#pragma unroll
            for (int i = 0; i < 8; ++i)
                xs[i] = __shfl_sync(0xffffffffu, xval, i, 8);

            float4 sp;
            float* spv = &sp.x;
#pragma unroll
            for (int r = 0; r < 4; ++r) {
                float p[8];
#pragma unroll
                for (int i = 0; i < 8; ++i)
                    p[i] = __fmul_rn(w1[r][i], xs[i]);
                float c = __fadd_rn(butterfly8(p), bias1[r]);
                lif(m1[r], c, spv[r]);
            }

            *reinterpret_cast<float4*>(&s1buf[slot][grow][4 * j]) = sp;
            if (j < 7)
                *reinterpret_cast<float4*>(spk1p) = sp;
            spk1p += S1STRIDE;
        };

        for (int tb = 0; tb < T_STEPS; tb += 4) {
            const float a0 = pf0, a1 = pf1, a2 = pf2, a3 = pf3;
            if (tb + 4 < T_STEPS) {
                const float* p = xp + (size_t)(tb + 4) * xstride;
                pf0 = p[0];
                pf1 = p[xstride];
                pf2 = p[2 * xstride];
                pf3 = p[3 * xstride];
            }
            const int s0 = tb & 7;
            stepA(a0, s0 + 0);
            stepA(a1, s0 + 1);
            stepA(a2, s0 + 2);
            stepA(a3, s0 + 3);
            bar_pair(barid);   // publish 4 slots (drains STS)
        }
    } else {
        // ====== WARP B: layers 2 + 3; consumes 4 slots per barrier ======
        float w2[NH1];
#pragma unroll
        for (int k = 0; k < NH1; ++k) w2[k] = __ldg(&W2[j * NH1 + k]);
        const float bias2 = __ldg(&b2[j]);

        const bool j4 = (j < 4);
        float w3[8];
#pragma unroll
        for (int i = 0; i < 8; ++i) w3[i] = j4 ? __ldg(&W3[j * NH2 + i]) : 0.0f;
        const float bias3 = j4 ? __ldg(&b3[j]) : 0.0f;

        float m2 = 0.f, m3 = 0.f;

        float* mem3p = out                                  + (size_t)b * NOUT + j;
        float* spk3p = out + (size_t)T_STEPS * BATCH * NOUT + (size_t)b * NOUT + j;
        float* spk2p = out + 2ull * T_STEPS * BATCH * NOUT
                           + (size_t)T_STEPS * BATCH * NH1  + (size_t)b * NH2 + j;

        const int gsh = g << 3;   // ballot byte shift for this group

        auto stepB = [&](int slot) {
            float s1v[28];
#pragma unroll
            for (int q = 0; q < 7; ++q) {
                float4 s = *reinterpret_cast<const float4*>(&s1buf[slot][grow][4 * q]);
                s1v[4 * q + 0] = s.x; s1v[4 * q + 1] = s.y;
                s1v[4 * q + 2] = s.z; s1v[4 * q + 3] = s.w;
            }
            // width-32 butterfly; LEAF FFMA-folded (products exact for 0/1 spikes)
            float q0[16];
#pragma unroll
            for (int i = 0; i < 12; ++i)
                q0[i] = __fmaf_rn(w2[i], s1v[i], __fmul_rn(w2[i + 16], s1v[i + 16]));
#pragma unroll
            for (int i = 12; i < 16; ++i)
                q0[i] = __fmul_rn(w2[i], s1v[i]);
            float r0[8];
#pragma unroll
            for (int i = 0; i < 8; ++i) r0[i] = __fadd_rn(q0[i], q0[i + 8]);
            float s4[4];
#pragma unroll
            for (int i = 0; i < 4; ++i) s4[i] = __fadd_rn(r0[i], r0[i + 4]);
            float t0 = __fadd_rn(s4[0], s4[2]);
            float t1 = __fadd_rn(s4[1], s4[3]);
            float a2 = __fadd_rn(__fadd_rn(t0, t1), bias2);

            // LIF layer 2 (inline so the spike predicate is reusable)
            const float mo2 = m2;
            float mn2 = __fmaf_rn(0.9f, mo2, a2);
            if (mo2 > 1.0f) mn2 = __fsub_rn(mn2, 1.0f);
            m2 = mn2;
            const bool sp2 = (mn2 > 1.0f);
            *spk2p = sp2 ? 1.0f : 0.0f;
            spk2p += S2STRIDE;

            // layer 3 via ballot: product w3[i]*s2[i] == (bit ? w3[i] : 0)
            // (+/-0 differences are absorbed before any comparator/output)
            const unsigned bal = __ballot_sync(0xffffffffu, sp2);
            const unsigned byte = bal >> gsh;
            float p3[8];
#pragma unroll
            for (int i = 0; i < 8; ++i)
                p3[i] = (byte & (1u << i)) ? w3[i] : 0.0f;
            float a3 = __fadd_rn(butterfly8(p3), bias3);

            float s3;
            lif(m3, a3, s3);
            if (j4) {
                *mem3p = m3;
                *spk3p = s3;
            }
            mem3p += O3STRIDE;
            spk3p += O3STRIDE;
        };

        for (int tb = 0; tb < T_STEPS; tb += 4) {
            bar_pair(barid);   // wait for warp A's 4 slots
            const int s0 = tb & 7;
            stepB(s0 + 0);
            stepB(s0 + 1);
            stepB(s0 + 2);
            stepB(s0 + 3);
        }
    }
}

extern "C" void kernel_launch(void* const* d_in, const int* in_sizes, int n_in,
                              void* d_out, int out_size) {
    const float* x  = (const float*)d_in[0];
    const float* W1 = (const float*)d_in[1];
    const float* b1 = (const float*)d_in[2];
    const float* W2 = (const float*)d_in[3];
    const float* b2 = (const float*)d_in[4];
    const float* W3 = (const float*)d_in[5];
    const float* b3 = (const float*)d_in[6];

    const int blocks = BATCH / BATCHES_PER_BLOCK;  // 256
    snn_kernel<<<blocks, BLOCK_THREADS>>>(x, W1, b1, W2, b2, W3, b3, (float*)d_out);
}